// round 17
// baseline (speedup 1.0000x reference)
#include <cuda_runtime.h>
#include <cuda_fp16.h>
#include <cstdint>

#define NB   8192
#define NS   100
#define NE   64
#define NH1  128
#define NH2  64
#define NTHREADS 896   // 28 warps: 7 m-groups (32 rows) x 4 n-groups, M-tile 224

// ---- smem layout (bytes) ----
#define A_SZ      57344             // one A buffer [224 x 128k] fp16 swizzled nar=28
#define OFF_A     0                 // A[2] double buffer (114688)
#define OFF_B1    114688            // B1 fp16 (32768)
#define OFF_B2    147456            // B2 fp16 (16384)
#define OFF_W2    163840            // W2[64] f32
#define OFF_B1B   164096            // b1[64] f32
#define OFF_C     164352            // c[2 parity][256] f32 (2048)
#define OFF_SCORE 166400            // scores[2 parity][256] f32 (2048)
#define OFF_PART  168448            // score partials [224][4] f32 (3584)
#define OFF_POUT  172032            // out partials [2][2][64] f32 (1024)
#define SMEM_TOTAL 173056

// ---- device scratch: pre-folded, pre-swizzled fp16 weights ----
__device__ uint4 g_B1[2048];      // 32KB, [128n][128k] swizzled nar=16
__device__ uint4 g_B2[1024];      // 16KB, [64n][128k]  swizzled nar=8
__device__ float g_Wq[NE * NH1];  // [e][h] = W0a + W0d

// ================= helpers =================
__device__ __forceinline__ uint32_t smem_u32(const void* p) {
    uint32_t a;
    asm("{ .reg .u64 t; cvta.to.shared.u64 t, %1; cvt.u32.u64 %0, t; }" : "=r"(a) : "l"(p));
    return a;
}
__device__ __forceinline__ void ldsm4(uint32_t* r, uint32_t addr) {
    asm volatile("ldmatrix.sync.aligned.m8n8.x4.shared.b16 {%0,%1,%2,%3}, [%4];"
                 : "=r"(r[0]), "=r"(r[1]), "=r"(r[2]), "=r"(r[3]) : "r"(addr));
}
__device__ __forceinline__ void mma_f16(float* c, const uint32_t* a, uint32_t b0, uint32_t b1) {
    asm volatile("mma.sync.aligned.m16n8k16.row.col.f32.f16.f16.f32 "
                 "{%0,%1,%2,%3}, {%4,%5,%6,%7}, {%8,%9}, {%0,%1,%2,%3};"
                 : "+f"(c[0]), "+f"(c[1]), "+f"(c[2]), "+f"(c[3])
                 : "r"(a[0]), "r"(a[1]), "r"(a[2]), "r"(a[3]), "r"(b0), "r"(b1));
}
__device__ __forceinline__ uint32_t cvt_f16x2(float x0, float x1) {
    uint32_t r;
    asm("cvt.rn.f16x2.f32 %0, %1, %2;" : "=r"(r) : "f"(x1), "f"(x0));
    return r;
}
__device__ __forceinline__ uint32_t hmul2(uint32_t a, uint32_t b) {
    uint32_t r;
    asm("mul.rn.f16x2 %0, %1, %2;" : "=r"(r) : "r"(a), "r"(b));
    return r;
}
// swizzled byte offset in one A buffer (nar=28): row 0..223, k elem 0..127
__device__ __forceinline__ uint32_t boffA(int row, int k) {
    return (uint32_t)((((row >> 3) + (k >> 6) * 28) << 10) + ((row & 7) << 7)
                      + ((((k & 63) << 1)) ^ ((row & 7) << 4)));
}
__device__ __forceinline__ uint32_t boffB(int n, int k, int nar) {
    return (uint32_t)((((n >> 3) + (k >> 6) * nar) << 10) + ((n & 7) << 7)
                      + ((((k & 63) << 1)) ^ ((n & 7) << 4)));
}

// ================= prep: fold + fp16 + swizzle weights =================
__global__ void prep_kernel(const float* __restrict__ W0, const float* __restrict__ W1) {
    int gid = blockIdx.x * blockDim.x + threadIdx.x;
    if (gid < 16384) {                 // B1: n=h, k=f -> Wcat[f][h]
        int n = gid >> 7, k = gid & 127;
        float v;
        if (k < 64) v = W0[(64 + k) * NH1 + n] - W0[(192 + k) * NH1 + n];
        else        v = W0[(128 + (k - 64)) * NH1 + n];
        *(__half*)((char*)&g_B1[0] + boffB(n, k, 16)) = __float2half_rn(v);
    } else if (gid < 24576) {          // B2: n=j, k=h -> W1[h][j]
        int i = gid - 16384;
        int n = i >> 7, k = i & 127;
        *(__half*)((char*)&g_B2[0] + boffB(n, k, 8)) = __float2half_rn(W1[k * NH2 + n]);
    } else if (gid < 32768) {
        int i = gid - 24576;
        int e = i >> 7, hh = i & 127;
        g_Wq[e * NH1 + hh] = W0[e * NH1 + hh] + W0[(192 + e) * NH1 + hh];
    }
}

// ====== persistent pipelined kernel: 896 threads, 2 batches/iter ======
__global__ __launch_bounds__(NTHREADS, 1)
void din_kernel(const float* __restrict__ q_g,
                const float* __restrict__ keys_g,
                const int*   __restrict__ klen_g,
                const float* __restrict__ b0_g,
                const float* __restrict__ b1_g,
                const float* __restrict__ W2_g,
                const float* __restrict__ b2_g,
                float* __restrict__ out_g,
                float* __restrict__ attn_g,
                int npairs) {
    extern __shared__ char smem[];
    const uint32_t sbase = smem_u32(smem);
    float* sW2    = (float*)(smem + OFF_W2);
    float* sB1b   = (float*)(smem + OFF_B1B);
    float* sC     = (float*)(smem + OFF_C);      // [parity][256]
    float* sScore = (float*)(smem + OFF_SCORE);  // [parity][256]
    float* sPart  = (float*)(smem + OFF_PART);
    float* sPOut  = (float*)(smem + OFF_POUT);

    const int t = threadIdx.x;
    const int lane = t & 31, w = t >> 5;
    const float b2v = b2_g[0];

    // ---- weights -> smem ONCE ----
    {
        uint4* d1 = (uint4*)(smem + OFF_B1);
        for (int i = t; i < 2048; i += NTHREADS) d1[i] = g_B1[i];
        uint4* d2 = (uint4*)(smem + OFF_B2);
        for (int i = t; i < 1024; i += NTHREADS) d2[i] = g_B2[i];
        if (t < 64) { sW2[t] = W2_g[t]; sB1b[t] = b1_g[t]; }
    }
    // zero pad rows 200..223 in BOTH A buffers, once
    for (int i = t; i < 24 * 64 * 2; i += NTHREADS) {
        int buf = (i >= 24 * 64), rr = (i % (24 * 64)) >> 6, kk = (i & 63) * 2;
        *(uint32_t*)(smem + OFF_A + buf * A_SZ + boffA(200 + rr, kk)) = 0u;
    }
    __syncthreads();

    // ---- lane geometry ----
    const int mg = w >> 2, ng = w & 3;
    const int s0 = mg * 32;
    const int rA = s0 + (lane & 15);
    const uint32_t aRowPart = ((rA >> 3) << 10) + ((rA & 7) << 7);
    const uint32_t hsxA = (((lane >> 4) & 1) * 16) ^ ((lane & 7) << 4);
    const uint32_t hsxB = (((lane >> 3) & 1) * 16) ^ ((lane & 7) << 4);
    const int h0 = ng * 32, j0 = ng * 16;
    const uint32_t b1Base = sbase + OFF_B1 + (((h0 >> 3) + ((lane >> 4) & 1)) << 10)
                          + ((lane & 7) << 7);
    const uint32_t b2Base = sbase + OFF_B2 + (((j0 >> 3) + ((lane >> 4) & 1)) << 10)
                          + ((lane & 7) << 7);

    int i = 0;
    long prev_gb0 = 0;
    for (int p = blockIdx.x; p < npairs; p += gridDim.x, i++) {
        const int cur = i & 1, nxt = cur ^ 1;
        const long gb0 = (long)p * 2;
        const int nextP = p + gridDim.x;
        const bool hasNext = (nextP < npairs);
        const long ngb0 = (long)nextP * 2;
        char* aCur = smem + OFF_A + cur * A_SZ;
        char* aNxt = smem + OFF_A + nxt * A_SZ;
        const uint32_t aBase = sbase + OFF_A + (uint32_t)cur * A_SZ + aRowPart;

        if (i == 0) {
            // ---- prologue: build(p) + c(p) ----
            for (int it = t; it < 3200; it += NTHREADS) {
                int batch = (it >= 1600), rem = it - batch * 1600;
                int s = rem >> 4, q = rem & 15;
                int row = batch * 100 + s;
                float4 kv = *(const float4*)&keys_g[((gb0 + batch) * NS + s) * NE + 4 * q];
                float4 qv = *(const float4*)&q_g[(gb0 + batch) * NE + 4 * q];
                uint2 w0;
                w0.x = cvt_f16x2(kv.x, kv.y);
                w0.y = cvt_f16x2(kv.z, kv.w);
                *(uint2*)(aCur + boffA(row, 4 * q)) = w0;
                uint2 w1;
                w1.x = cvt_f16x2(kv.x * qv.x, kv.y * qv.y);
                w1.y = cvt_f16x2(kv.z * qv.z, kv.w * qv.w);
                *(uint2*)(aCur + boffA(row, 64 + 4 * q)) = w1;
            }
            if (t < 256) {
                int batch = t >> 7, h = t & 127;
                const float* qb = q_g + (gb0 + batch) * NE;
                float a0 = b0_g[h];
                #pragma unroll 8
                for (int e = 0; e < NE; e++) a0 = fmaf(qb[e], g_Wq[e * NH1 + h], a0);
                sC[cur * 256 + t] = a0;
            }
            __syncthreads();
        }

        // ---- out(prev) hidden under GEMM1: warps 0-7 ----
        if (i > 0 && w < 8) {
            const int pb = t >> 7, rem = t & 127, g = rem >> 6, e = rem & 63;
            const float* kb = keys_g + (prev_gb0 + pb) * NS * NE;
            const float* sc = sScore + nxt * 256 + pb * 128;   // prev parity == nxt
            float a = 0.f;
            for (int s = g; s < NS; s += 2) a = fmaf(sc[s], kb[s * NE + e], a);
            sPOut[pb * 128 + g * 64 + e] = a;
            asm volatile("bar.sync 3, 256;" ::: "memory");
            if (t < 128) {
                const int bb = t >> 6, ee = t & 63;
                out_g[(prev_gb0 + bb) * NE + ee] =
                    sPOut[bb * 128 + ee] + sPOut[bb * 128 + 64 + ee];
            }
        }

        // ================= GEMM1: D1[224 x 128] = Kp @ Wcat =================
        float acc[8][4];
        #pragma unroll
        for (int a_ = 0; a_ < 8; a_++)
            #pragma unroll
            for (int b_ = 0; b_ < 4; b_++) acc[a_][b_] = 0.f;

        #pragma unroll
        for (int k = 0; k < 8; k++) {
            const uint32_t kbA = ((k < 4) ? k * 32u : 28672u + (k - 4) * 32u) ^ hsxA;
            const uint32_t kbB = ((k < 4) ? k * 32u : 16384u + (k - 4) * 32u) ^ hsxB;
            uint32_t ah0[4], ah1[4];
            ldsm4(ah0, aBase + kbA);
            ldsm4(ah1, aBase + 2048 + kbA);
            #pragma unroll
            for (int np = 0; np < 2; np++) {
                uint32_t bh[4];
                ldsm4(bh, b1Base + np * 2048 + kbB);
                const int nt = np * 2;
                mma_f16(acc[nt],         ah0, bh[0], bh[1]);
                mma_f16(acc[nt + 1],     ah0, bh[2], bh[3]);
                mma_f16(acc[4 + nt],     ah1, bh[0], bh[1]);
                mma_f16(acc[4 + nt + 1], ah1, bh[2], bh[3]);
            }
        }
        __syncthreads();

        // ---- epilogue1: H0 = relu(D1 + c) -> fp16 -> A[cur] ----
        #pragma unroll
        for (int mt = 0; mt < 2; mt++) {
            const int row = s0 + mt * 16 + (lane >> 2);
            const int cb0 = cur * 256 + (row >= 100 ? 128 : 0);
            const int cb8 = cur * 256 + (row + 8 >= 100 ? 128 : 0);
            #pragma unroll
            for (int nt = 0; nt < 4; nt++) {
                const float* c = acc[mt * 4 + nt];
                const int col = h0 + nt * 8 + (lane & 3) * 2;
                const float c0 = sC[cb0 + col], c1 = sC[cb0 + col + 1];
                const float d0 = sC[cb8 + col], d1 = sC[cb8 + col + 1];
                *(uint32_t*)(aCur + boffA(row, col)) =
                    cvt_f16x2(fmaxf(c[0] + c0, 0.f), fmaxf(c[1] + c1, 0.f));
                *(uint32_t*)(aCur + boffA(row + 8, col)) =
                    cvt_f16x2(fmaxf(c[2] + d0, 0.f), fmaxf(c[3] + d1, 0.f));
            }
        }
        __syncthreads();

        // ======== GEMM2 (+ build(p+1) prefetch hidden inside) ========
        // prefetch: issue keys LDGs now, consume after the k-loop
        const bool dopf = hasNext && (t < 800);
        float4 kr0, kr1, kr2, kr3;
        uint32_t qh[8];
        int pf_row = 0, pf_qg = 0;
        if (dopf) {
            const int batch = (t >= 400), rem = t - batch * 400;
            const int s = rem >> 2;
            pf_qg = (rem & 3) * 16;
            pf_row = batch * 100 + s;
            const float4* kp4 = (const float4*)&keys_g[((ngb0 + batch) * NS + s) * NE + pf_qg];
            kr0 = kp4[0]; kr1 = kp4[1]; kr2 = kp4[2]; kr3 = kp4[3];
            const float4* qp4 = (const float4*)&q_g[(ngb0 + batch) * NE + pf_qg];
            float4 q0 = qp4[0], q1 = qp4[1], q2 = qp4[2], q3 = qp4[3];
            qh[0] = cvt_f16x2(q0.x, q0.y); qh[1] = cvt_f16x2(q0.z, q0.w);
            qh[2] = cvt_f16x2(q1.x, q1.y); qh[3] = cvt_f16x2(q1.z, q1.w);
            qh[4] = cvt_f16x2(q2.x, q2.y); qh[5] = cvt_f16x2(q2.z, q2.w);
            qh[6] = cvt_f16x2(q3.x, q3.y); qh[7] = cvt_f16x2(q3.z, q3.w);
        }

        float acc2[4][4];
        #pragma unroll
        for (int a_ = 0; a_ < 4; a_++)
            #pragma unroll
            for (int b_ = 0; b_ < 4; b_++) acc2[a_][b_] = 0.f;

        #pragma unroll
        for (int k = 0; k < 8; k++) {
            const uint32_t kbA = ((k < 4) ? k * 32u : 28672u + (k - 4) * 32u) ^ hsxA;
            const uint32_t kbB = ((k < 4) ? k * 32u : 8192u + (k - 4) * 32u) ^ hsxB;
            uint32_t ah0[4], ah1[4];
            ldsm4(ah0, aBase + kbA);
            ldsm4(ah1, aBase + 2048 + kbA);
            uint32_t bh[4];
            ldsm4(bh, b2Base + kbB);
            mma_f16(acc2[0], ah0, bh[0], bh[1]);
            mma_f16(acc2[1], ah0, bh[2], bh[3]);
            mma_f16(acc2[2], ah1, bh[0], bh[1]);
            mma_f16(acc2[3], ah1, bh[2], bh[3]);
        }

        // consume prefetch: convert + store into A[nxt]
        if (dopf) {
            uint32_t kp[8];
            kp[0] = cvt_f16x2(kr0.x, kr0.y); kp[1] = cvt_f16x2(kr0.z, kr0.w);
            kp[2] = cvt_f16x2(kr1.x, kr1.y); kp[3] = cvt_f16x2(kr1.z, kr1.w);
            kp[4] = cvt_f16x2(kr2.x, kr2.y); kp[5] = cvt_f16x2(kr2.z, kr2.w);
            kp[6] = cvt_f16x2(kr3.x, kr3.y); kp[7] = cvt_f16x2(kr3.z, kr3.w);
            uint4 v0 = make_uint4(kp[0], kp[1], kp[2], kp[3]);
            uint4 v1 = make_uint4(kp[4], kp[5], kp[6], kp[7]);
            *(uint4*)(aNxt + boffA(pf_row, pf_qg)) = v0;
            *(uint4*)(aNxt + boffA(pf_row, pf_qg + 8)) = v1;
            uint4 u0 = make_uint4(hmul2(kp[0], qh[0]), hmul2(kp[1], qh[1]),
                                  hmul2(kp[2], qh[2]), hmul2(kp[3], qh[3]));
            uint4 u1 = make_uint4(hmul2(kp[4], qh[4]), hmul2(kp[5], qh[5]),
                                  hmul2(kp[6], qh[6]), hmul2(kp[7], qh[7]));
            *(uint4*)(aNxt + boffA(pf_row, 64 + pf_qg)) = u0;
            *(uint4*)(aNxt + boffA(pf_row, 64 + pf_qg + 8)) = u1;
        }

        // ---- epilogue2: partial scores -> sPart ----
        {
            float part[4] = {0.f, 0.f, 0.f, 0.f};
            #pragma unroll
            for (int mt = 0; mt < 2; mt++) {
                #pragma unroll
                for (int nt = 0; nt < 2; nt++) {
                    const float* c = acc2[mt * 2 + nt];
                    const int col = j0 + nt * 8 + (lane & 3) * 2;
                    const float bb0 = sB1b[col], bb1 = sB1b[col + 1];
                    const float w0v = sW2[col], w1v = sW2[col + 1];
                    part[mt * 2]     += fmaxf(c[0] + bb0, 0.f) * w0v + fmaxf(c[1] + bb1, 0.f) * w1v;
                    part[mt * 2 + 1] += fmaxf(c[2] + bb0, 0.f) * w0v + fmaxf(c[3] + bb1, 0.f) * w1v;
                }
            }
            #pragma unroll
            for (int ii = 0; ii < 4; ii++) {
                float v = part[ii];
                v += __shfl_xor_sync(0xffffffffu, v, 1);
                v += __shfl_xor_sync(0xffffffffu, v, 2);
                if ((lane & 3) == 0) {
                    const int row = s0 + (ii >> 1) * 16 + (lane >> 2) + (ii & 1) * 8;
                    sPart[row * 4 + ng] = v;
                }
            }
        }
        __syncthreads();

        // ---- phase4: softmax(p) [w0-1]  ||  c(p+1) [w2-9] ----
        if (t < 64) {
            const int batch = t >> 5;
            float* sc = sScore + cur * 256 + batch * 128;
            const float* pp = sPart + batch * 400;
            const int len = klen_g[gb0 + batch];
            float m = -1e30f;
            float sv[4];
            #pragma unroll
            for (int ii = 0; ii < 4; ii++) {
                int s = lane + ii * 32;
                float v = -1e30f;
                if (s < NS) {
                    v = pp[s * 4] + pp[s * 4 + 1] + pp[s * 4 + 2] + pp[s * 4 + 3] + b2v;
                    if (s >= len) v = -1e30f;
                }
                sv[ii] = v;
                m = fmaxf(m, v);
            }
            #pragma unroll
            for (int off = 16; off; off >>= 1)
                m = fmaxf(m, __shfl_xor_sync(0xffffffffu, m, off));
            float sum = 0.f;
            #pragma unroll
            for (int ii = 0; ii < 4; ii++) {
                int s = lane + ii * 32;
                float v = (s < len) ? expf(sv[ii] - m) : 0.f;
                sv[ii] = v;
                sum += v;
            }
            #pragma unroll
            for (int off = 16; off; off >>= 1)
                sum += __shfl_xor_sync(0xffffffffu, sum, off);
            float inv = 1.f / sum;
            #pragma unroll
            for (int ii = 0; ii < 4; ii++) {
                int s = lane + ii * 32;
                if (s < NS) {
                    float a = sv[ii] * inv;
                    sc[s] = a;
                    if (attn_g) attn_g[(gb0 + batch) * NS + s] = a;
                }
            }
        } else if (hasNext && t < 320) {
            const int tt = t - 64, batch = tt >> 7, h = tt & 127;
            const float* qb = q_g + (ngb0 + batch) * NE;
            float a0 = b0_g[h];
            #pragma unroll 8
            for (int e = 0; e < NE; e++) a0 = fmaf(qb[e], g_Wq[e * NH1 + h], a0);
            sC[nxt * 256 + tt] = a0;
        }
        __syncthreads();
        prev_gb0 = gb0;
    }

    // ---- final out for the last pair ----
    if (i > 0 && w < 8) {
        const int prevpar = (i - 1) & 1;
        const int pb = t >> 7, rem = t & 127, g = rem >> 6, e = rem & 63;
        const float* kb = keys_g + (prev_gb0 + pb) * NS * NE;
        const float* sc = sScore + prevpar * 256 + pb * 128;
        float a = 0.f;
        for (int s = g; s < NS; s += 2) a = fmaf(sc[s], kb[s * NE + e], a);
        sPOut[pb * 128 + g * 64 + e] = a;
        asm volatile("bar.sync 3, 256;" ::: "memory");
        if (t < 128) {
            const int bb = t >> 6, ee = t & 63;
            out_g[(prev_gb0 + bb) * NE + ee] =
                sPOut[bb * 128 + ee] + sPOut[bb * 128 + 64 + ee];
        }
    }
}

extern "C" void kernel_launch(void* const* d_in, const int* in_sizes, int n_in,
                              void* d_out, int out_size) {
    const float* query = (const float*)d_in[0];
    const float* keys  = (const float*)d_in[1];
    const int*   klen  = (const int*)  d_in[2];
    const float* W0    = (const float*)d_in[3];
    const float* b0    = (const float*)d_in[4];
    const float* W1    = (const float*)d_in[5];
    const float* b1    = (const float*)d_in[6];
    const float* W2    = (const float*)d_in[7];
    const float* b2    = (const float*)d_in[8];

    float* outp  = (float*)d_out;
    float* attnp = (out_size >= NB * NE + NB * NS) ? outp + (size_t)NB * NE : nullptr;

    int dev = 0, nsm = 148;
    cudaGetDevice(&dev);
    cudaDeviceGetAttribute(&nsm, cudaDevAttrMultiProcessorCount, dev);

    cudaFuncSetAttribute(din_kernel, cudaFuncAttributeMaxDynamicSharedMemorySize, SMEM_TOTAL);

    prep_kernel<<<64, 512>>>(W0, W1);
    din_kernel<<<nsm, NTHREADS, SMEM_TOTAL>>>(query, keys, klen, b0, b1, W2, b2,
                                              outp, attnp, NB / 2);
}